// round 2
// baseline (speedup 1.0000x reference)
#include <cuda_runtime.h>
#include <cuda_bf16.h>

#define N_COARSE 100000
#define M_FINE   400000
#define C_IN     32
#define C_HID    64
#define C_OUT    32
#define K3       27

typedef unsigned long long ull;

// ---------------- scratch (static device globals; no allocation) ----------------
__device__ float g_bufA[N_COARSE * C_HID];   // 25.6 MB
__device__ float g_bufB[N_COARSE * C_HID];   // 25.6 MB
__device__ int   g_cnt[8];
__device__ int   g_list[8 * M_FINE];         // 12.8 MB bucket lists

// ---------------- helpers ----------------
__device__ __forceinline__ ull ffma2(ull a, ull b, ull c) {
    ull d;
    asm("fma.rn.f32x2 %0, %1, %2, %3;" : "=l"(d) : "l"(a), "l"(b), "l"(c));
    return d;
}
__device__ __forceinline__ ull pack2(float lo, float hi) {
    ull r;
    asm("mov.b64 %0, {%1, %2};" : "=l"(r) : "f"(lo), "f"(hi));
    return r;
}
__device__ __forceinline__ float2 unpack2(ull v) {
    float2 r;
    asm("mov.b64 {%0, %1}, %2;" : "=f"(r.x), "=f"(r.y) : "l"(v));
    return r;
}
__device__ __forceinline__ unsigned smem_u32(const void* p) {
    return (unsigned)__cvta_generic_to_shared(p);
}
__device__ __forceinline__ void cp_async16(unsigned dst, const void* src, int src_bytes) {
    asm volatile("cp.async.cg.shared.global [%0], [%1], 16, %2;"
                 :: "r"(dst), "l"(src), "r"(src_bytes));
}

// ---------------- reset + bucket (group fine voxels by t-conv offset) ----------------
__global__ void reset_kernel() {
    if (threadIdx.x < 8) g_cnt[threadIdx.x] = 0;
}

__global__ void __launch_bounds__(256)
bucket_kernel(const int* __restrict__ offs) {
    int m = blockIdx.x * 256 + threadIdx.x;
    unsigned active = __ballot_sync(0xffffffffu, m < M_FINE);
    if (m < M_FINE) {
        int off = offs[m] & 7;
        unsigned mask = __match_any_sync(active, off);
        int lane = threadIdx.x & 31;
        int leader = __ffs(mask) - 1;
        int rank = __popc(mask & ((1u << lane) - 1u));
        int base = 0;
        if (lane == leader) base = atomicAdd(&g_cnt[off], __popc(mask));
        base = __shfl_sync(mask, base, leader);
        g_list[off * M_FINE + base + rank] = m;
    }
}

// ---------------- sparse 3x3x3 conv (cp.async double-buffered, 4vox x 8cout/thread) ----------------
// 128 threads, 64 voxels per block. smem x tile padded to stride CIN+4.
template <int CIN>
__global__ void __launch_bounds__(128)
conv3_pipe(const float* __restrict__ x, const int* __restrict__ nbr,
           const float* __restrict__ W, const float* __restrict__ b,
           float* __restrict__ out) {
    constexpr int CINP = CIN + 4;
    extern __shared__ float dsm[];
    float* sW = dsm;                          // 2 * CIN*64
    float* sX = sW + 2 * CIN * 64;            // 2 * 64*CINP
    int* sidx = (int*)(sX + 2 * 64 * CINP);   // 64*27

    const int tid = threadIdx.x;
    const int tx  = tid & 7;      // 8 cout groups of 8
    const int ty  = tid >> 3;     // 16 voxel groups of 4
    const int vb  = blockIdx.x * 64;
    int nval = N_COARSE - vb; if (nval > 64) nval = 64;

    for (int i = tid; i < 64 * K3; i += 128)
        sidx[i] = (i < nval * K3) ? nbr[vb * K3 + i] : N_COARSE;
    __syncthreads();

    auto issue = [&](int k, int buf) {
        const float* Wk = W + k * CIN * 64;
        float* wdst = sW + buf * CIN * 64;
        #pragma unroll
        for (int r = 0; r < (CIN * 16) / 128; ++r) {
            int i = tid + 128 * r;
            cp_async16(smem_u32(wdst + i * 4), Wk + i * 4, 16);
        }
        float* xdst = sX + buf * 64 * CINP;
        #pragma unroll
        for (int r = 0; r < (64 * CIN / 4) / 128; ++r) {
            int i = tid + 128 * r;
            int v = i / (CIN / 4), c4 = i % (CIN / 4);
            int idx = sidx[v * K3 + k];
            bool ok = idx < N_COARSE;
            const float* src = ok ? (x + idx * CIN + c4 * 4) : x;
            cp_async16(smem_u32(xdst + v * CINP + c4 * 4), src, ok ? 16 : 0);
        }
        asm volatile("cp.async.commit_group;");
    };

    ull acc[16];
    #pragma unroll
    for (int i = 0; i < 16; ++i) acc[i] = 0ull;

    issue(0, 0);
    for (int k = 0; k < K3; ++k) {
        if (k < K3 - 1) {
            issue(k + 1, (k + 1) & 1);
            asm volatile("cp.async.wait_group 1;");
        } else {
            asm volatile("cp.async.wait_group 0;");
        }
        __syncthreads();
        const float* cw = sW + (k & 1) * CIN * 64;
        const float* cx = sX + (k & 1) * 64 * CINP;
        #pragma unroll
        for (int c = 0; c < CIN; c += 4) {
            float4 xs[4];
            #pragma unroll
            for (int i = 0; i < 4; ++i)
                xs[i] = *(const float4*)(cx + (ty * 4 + i) * CINP + c);
            #pragma unroll
            for (int cc = 0; cc < 4; ++cc) {
                float4 w0 = *(const float4*)(cw + (c + cc) * 64 + tx * 8);
                float4 w1 = *(const float4*)(cw + (c + cc) * 64 + tx * 8 + 4);
                ull wa = pack2(w0.x, w0.y), wb = pack2(w0.z, w0.w);
                ull wc = pack2(w1.x, w1.y), wd = pack2(w1.z, w1.w);
                #pragma unroll
                for (int i = 0; i < 4; ++i) {
                    float xv = ((const float*)&xs[i])[cc];
                    ull xx = pack2(xv, xv);
                    acc[4 * i + 0] = ffma2(xx, wa, acc[4 * i + 0]);
                    acc[4 * i + 1] = ffma2(xx, wb, acc[4 * i + 1]);
                    acc[4 * i + 2] = ffma2(xx, wc, acc[4 * i + 2]);
                    acc[4 * i + 3] = ffma2(xx, wd, acc[4 * i + 3]);
                }
            }
        }
        __syncthreads();
    }

    float4 b0 = *(const float4*)(b + tx * 8);
    float4 b1 = *(const float4*)(b + tx * 8 + 4);
    #pragma unroll
    for (int i = 0; i < 4; ++i) {
        int v = vb + ty * 4 + i;
        if (v < N_COARSE) {
            float2 r0 = unpack2(acc[4 * i + 0]);
            float2 r1 = unpack2(acc[4 * i + 1]);
            float2 r2 = unpack2(acc[4 * i + 2]);
            float2 r3 = unpack2(acc[4 * i + 3]);
            float4 o0 = make_float4(fmaxf(r0.x + b0.x, 0.f), fmaxf(r0.y + b0.y, 0.f),
                                    fmaxf(r1.x + b0.z, 0.f), fmaxf(r1.y + b0.w, 0.f));
            float4 o1 = make_float4(fmaxf(r2.x + b1.x, 0.f), fmaxf(r2.y + b1.y, 0.f),
                                    fmaxf(r3.x + b1.z, 0.f), fmaxf(r3.y + b1.w, 0.f));
            *(float4*)(out + v * 64 + tx * 8)     = o0;
            *(float4*)(out + v * 64 + tx * 8 + 4) = o1;
        }
    }
}

// ---------------- shared 64x64 GEMM + bias + relu on a 64-voxel tile (stride-68 smem) ----------------
__device__ __forceinline__ void gemm64x64_relu(const float* __restrict__ sx,
                                               const float* __restrict__ sw,
                                               const float* __restrict__ sb,
                                               float* __restrict__ so,
                                               int tx, int ty) {
    ull acc[8];
    #pragma unroll
    for (int i = 0; i < 8; ++i) acc[i] = 0ull;
    #pragma unroll
    for (int c = 0; c < 64; c += 4) {
        float4 xs[4];
        #pragma unroll
        for (int i = 0; i < 4; ++i)
            xs[i] = *(const float4*)(sx + (ty * 4 + i) * 68 + c);
        #pragma unroll
        for (int cc = 0; cc < 4; ++cc) {
            float4 w = *(const float4*)(sw + (c + cc) * 64 + tx * 4);
            ull w01 = pack2(w.x, w.y), w23 = pack2(w.z, w.w);
            #pragma unroll
            for (int i = 0; i < 4; ++i) {
                float xv = ((const float*)&xs[i])[cc];
                ull xx = pack2(xv, xv);
                acc[2 * i]     = ffma2(xx, w01, acc[2 * i]);
                acc[2 * i + 1] = ffma2(xx, w23, acc[2 * i + 1]);
            }
        }
    }
    float2 b01 = *(const float2*)(sb + tx * 4);
    float2 b23 = *(const float2*)(sb + tx * 4 + 2);
    #pragma unroll
    for (int i = 0; i < 4; ++i) {
        float2 r01 = unpack2(acc[2 * i]);
        float2 r23 = unpack2(acc[2 * i + 1]);
        float4 o = make_float4(fmaxf(r01.x + b01.x, 0.f), fmaxf(r01.y + b01.y, 0.f),
                               fmaxf(r23.x + b23.x, 0.f), fmaxf(r23.y + b23.y, 0.f));
        *(float4*)(so + (ty * 4 + i) * 68 + tx * 4) = o;
    }
}

// ---------------- fused t-conv + decoder: per-offset bucketed GEMM pipeline ----------------
// grid = (GX, 8). Block keeps W_t[off], W_d1, W_d2, biases in smem; tiles of 64 fine voxels.
__global__ void __launch_bounds__(256)
fused_kernel(const float* __restrict__ x3, const int* __restrict__ parent,
             const float* __restrict__ Wt, const float* __restrict__ bt,
             const float* __restrict__ Wd1, const float* __restrict__ bd1,
             const float* __restrict__ Wd2, const float* __restrict__ bd2,
             const float* __restrict__ xup, float* __restrict__ out) {
    extern __shared__ float dsm[];
    float* sWt = dsm;              // 4096
    float* sW1 = sWt + 4096;       // 4096
    float* sW2 = sW1 + 4096;       // 2048
    float* sg  = sW2 + 2048;       // 64*68
    float* st  = sg + 64 * 68;     // 64*68
    float* sbt = st + 64 * 68;     // 64
    float* sb1 = sbt + 64;         // 64
    float* sb2 = sb1 + 64;         // 32
    int*   smv = (int*)(sb2 + 32); // 64
    int*   spv = smv + 64;         // 64

    const int tid = threadIdx.x;
    const int off = blockIdx.y;
    const int cnt = g_cnt[off];
    const int* list = g_list + off * M_FINE;

    // one-time weight/bias loads
    {
        const float4* w = (const float4*)(Wt + off * 4096);
        #pragma unroll
        for (int r = 0; r < 4; ++r) ((float4*)sWt)[tid + 256 * r] = w[tid + 256 * r];
        const float4* w1 = (const float4*)Wd1;
        #pragma unroll
        for (int r = 0; r < 4; ++r) ((float4*)sW1)[tid + 256 * r] = w1[tid + 256 * r];
        const float4* w2 = (const float4*)Wd2;
        #pragma unroll
        for (int r = 0; r < 2; ++r) ((float4*)sW2)[tid + 256 * r] = w2[tid + 256 * r];
        if (tid < 64) { sbt[tid] = bt[tid]; sb1[tid] = bd1[tid]; }
        if (tid < 32) sb2[tid] = bd2[tid];
    }

    const int tx = tid & 15, ty = tid >> 4;     // stage1/2 tiling
    const int tx3 = tid & 31, ty3 = tid >> 5;   // stage3 tiling

    for (int tile = blockIdx.x; tile * 64 < cnt; tile += gridDim.x) {
        __syncthreads();
        if (tid < 64) {
            int j = tile * 64 + tid;
            int m = (j < cnt) ? list[j] : -1;
            smv[tid] = m;
            spv[tid] = (m >= 0) ? parent[m] : N_COARSE;
        }
        __syncthreads();
        // gather parent features (64 rows x 64 ch)
        #pragma unroll
        for (int r = 0; r < 4; ++r) {
            int i = tid + 256 * r;
            int v = i >> 4, c4 = i & 15;
            int p = spv[v];
            float4 val = make_float4(0.f, 0.f, 0.f, 0.f);
            if (p < N_COARSE) val = *(const float4*)(x3 + p * 64 + c4 * 4);
            *(float4*)(sg + v * 68 + c4 * 4) = val;
        }
        __syncthreads();
        gemm64x64_relu(sg, sWt, sbt, st, tx, ty);   // t = relu(g @ Wt[off] + bt)
        __syncthreads();
        gemm64x64_relu(st, sW1, sb1, sg, tx, ty);   // y = relu(t @ Wd1 + bd1)
        __syncthreads();
        // stage3: z = y @ Wd2 + bd2; out = z + xup (voxel-pair packed)
        ull a[4];
        #pragma unroll
        for (int q = 0; q < 4; ++q) a[q] = 0ull;
        #pragma unroll
        for (int c = 0; c < 64; c += 4) {
            float4 ys[8];
            #pragma unroll
            for (int j = 0; j < 8; ++j)
                ys[j] = *(const float4*)(sg + (ty3 * 8 + j) * 68 + c);
            #pragma unroll
            for (int cc = 0; cc < 4; ++cc) {
                float w = sW2[(c + cc) * 32 + tx3];
                ull ww = pack2(w, w);
                #pragma unroll
                for (int q = 0; q < 4; ++q) {
                    float y0 = ((const float*)&ys[2 * q])[cc];
                    float y1 = ((const float*)&ys[2 * q + 1])[cc];
                    a[q] = ffma2(pack2(y0, y1), ww, a[q]);
                }
            }
        }
        float b2 = sb2[tx3];
        #pragma unroll
        for (int q = 0; q < 4; ++q) {
            float2 z = unpack2(a[q]);
            int v0 = ty3 * 8 + 2 * q;
            int m0 = smv[v0], m1 = smv[v0 + 1];
            if (m0 >= 0) out[m0 * 32 + tx3] = z.x + b2 + xup[m0 * 32 + tx3];
            if (m1 >= 0) out[m1 * 32 + tx3] = z.y + b2 + xup[m1 * 32 + tx3];
        }
    }
}

// ---------------- launch ----------------
extern "C" void kernel_launch(void* const* d_in, const int* in_sizes, int n_in,
                              void* d_out, int out_size) {
    const float* feats  = (const float*)d_in[0];   // [N,32]
    const float* xup    = (const float*)d_in[1];   // [M,32]
    const int*   nbr    = (const int*)d_in[2];     // [N,27]
    const int*   parent = (const int*)d_in[3];     // [M]
    const int*   offs   = (const int*)d_in[4];     // [M]
    const float* We1 = (const float*)d_in[5];
    const float* be1 = (const float*)d_in[6];
    const float* We2 = (const float*)d_in[7];
    const float* be2 = (const float*)d_in[8];
    const float* We3 = (const float*)d_in[9];
    const float* be3 = (const float*)d_in[10];
    const float* Wt  = (const float*)d_in[11];
    const float* bt  = (const float*)d_in[12];
    const float* Wd1 = (const float*)d_in[13];
    const float* bd1 = (const float*)d_in[14];
    const float* Wd2 = (const float*)d_in[15];
    const float* bd2 = (const float*)d_in[16];
    float* out = (float*)d_out;

    float *pA, *pB;
    cudaGetSymbolAddress((void**)&pA, g_bufA);
    cudaGetSymbolAddress((void**)&pB, g_bufB);

    const int smem32 = (2 * 32 * 64 + 2 * 64 * 36) * 4 + 64 * K3 * 4;   // 41728
    const int smem64 = (2 * 64 * 64 + 2 * 64 * 68) * 4 + 64 * K3 * 4;   // 74496
    const int smemF  = (4096 + 4096 + 2048 + 2 * 64 * 68 + 160) * 4 + 128 * 4;

    cudaFuncSetAttribute(conv3_pipe<32>, cudaFuncAttributeMaxDynamicSharedMemorySize, smem32);
    cudaFuncSetAttribute(conv3_pipe<64>, cudaFuncAttributeMaxDynamicSharedMemorySize, smem64);
    cudaFuncSetAttribute(fused_kernel,   cudaFuncAttributeMaxDynamicSharedMemorySize, smemF);

    reset_kernel<<<1, 32>>>();
    bucket_kernel<<<(M_FINE + 255) / 256, 256>>>(offs);

    const int nblk = (N_COARSE + 63) / 64;  // 1563
    conv3_pipe<32><<<nblk, 128, smem32>>>(feats, nbr, We1, be1, pA);
    conv3_pipe<64><<<nblk, 128, smem64>>>(pA,    nbr, We2, be2, pB);
    conv3_pipe<64><<<nblk, 128, smem64>>>(pB,    nbr, We3, be3, pA);

    fused_kernel<<<dim3(64, 8), 256, smemF>>>(pA, parent, Wt, bt, Wd1, bd1,
                                              Wd2, bd2, xup, out);
}

// round 3
// speedup vs baseline: 1.0093x; 1.0093x over previous
#include <cuda_runtime.h>
#include <cuda_bf16.h>

#define N_COARSE 100000
#define M_FINE   400000
#define C_IN     32
#define C_HID    64
#define C_OUT    32
#define K3       27

typedef unsigned long long ull;

// ---------------- scratch (static device globals; no allocation) ----------------
__device__ float g_bufA[N_COARSE * C_HID];   // 25.6 MB
__device__ float g_bufB[N_COARSE * C_HID];   // 25.6 MB
__device__ int   g_cnt[8];
__device__ int   g_list[8 * M_FINE];         // 12.8 MB bucket lists

// ---------------- helpers ----------------
__device__ __forceinline__ ull ffma2(ull a, ull b, ull c) {
    ull d;
    asm("fma.rn.f32x2 %0, %1, %2, %3;" : "=l"(d) : "l"(a), "l"(b), "l"(c));
    return d;
}
__device__ __forceinline__ ull pack2(float lo, float hi) {
    ull r;
    asm("mov.b64 %0, {%1, %2};" : "=l"(r) : "f"(lo), "f"(hi));
    return r;
}
__device__ __forceinline__ float2 unpack2(ull v) {
    float2 r;
    asm("mov.b64 {%0, %1}, %2;" : "=f"(r.x), "=f"(r.y) : "l"(v));
    return r;
}
__device__ __forceinline__ unsigned smem_u32(const void* p) {
    return (unsigned)__cvta_generic_to_shared(p);
}
__device__ __forceinline__ void cp_async16(unsigned dst, const void* src, int src_bytes) {
    asm volatile("cp.async.cg.shared.global [%0], [%1], 16, %2;"
                 :: "r"(dst), "l"(src), "r"(src_bytes));
}

// ---------------- reset + bucket (group fine voxels by t-conv offset) ----------------
__global__ void reset_kernel() {
    if (threadIdx.x < 8) g_cnt[threadIdx.x] = 0;
}

__global__ void __launch_bounds__(256)
bucket_kernel(const int* __restrict__ offs) {
    int m = blockIdx.x * 256 + threadIdx.x;
    unsigned active = __ballot_sync(0xffffffffu, m < M_FINE);
    if (m < M_FINE) {
        int off = offs[m] & 7;
        unsigned mask = __match_any_sync(active, off);
        int lane = threadIdx.x & 31;
        int leader = __ffs(mask) - 1;
        int rank = __popc(mask & ((1u << lane) - 1u));
        int base = 0;
        if (lane == leader) base = atomicAdd(&g_cnt[off], __popc(mask));
        base = __shfl_sync(mask, base, leader);
        g_list[off * M_FINE + base + rank] = m;
    }
}

// ---------------- sparse 3x3x3 conv (cp.async double-buffered) ----------------
// 256 threads, 64 voxels per block, thread computes 2 voxels x 8 couts
// (couts tx*4..+3 and 32+tx*4..+3 -> conflict-free 128B LDS.128 rows).
template <int CIN>
__global__ void __launch_bounds__(256)
conv3_pipe(const float* __restrict__ x, const int* __restrict__ nbr,
           const float* __restrict__ W, const float* __restrict__ b,
           float* __restrict__ out) {
    constexpr int CINP = CIN + 4;
    extern __shared__ float dsm[];
    float* sW = dsm;                          // 2 * CIN*64
    float* sX = sW + 2 * CIN * 64;            // 2 * 64*CINP
    int* sidx = (int*)(sX + 2 * 64 * CINP);   // 64*27

    const int tid = threadIdx.x;
    const int tx  = tid & 7;      // cout groups: tx*4 and 32+tx*4
    const int ty  = tid >> 3;     // voxel pair {2ty, 2ty+1}
    const int vb  = blockIdx.x * 64;
    int nval = N_COARSE - vb; if (nval > 64) nval = 64;

    for (int i = tid; i < 64 * K3; i += 256)
        sidx[i] = (i < nval * K3) ? nbr[vb * K3 + i] : N_COARSE;
    __syncthreads();

    auto issue = [&](int k, int buf) {
        const float* Wk = W + k * CIN * 64;
        float* wdst = sW + buf * CIN * 64;
        #pragma unroll
        for (int r = 0; r < (CIN * 16) / 256; ++r) {
            int i = tid + 256 * r;
            cp_async16(smem_u32(wdst + i * 4), Wk + i * 4, 16);
        }
        float* xdst = sX + buf * 64 * CINP;
        #pragma unroll
        for (int r = 0; r < (64 * CIN / 4) / 256; ++r) {
            int i = tid + 256 * r;
            int v = i / (CIN / 4), c4 = i % (CIN / 4);
            int idx = sidx[v * K3 + k];
            bool ok = idx < N_COARSE;
            const float* src = ok ? (x + idx * CIN + c4 * 4) : x;
            cp_async16(smem_u32(xdst + v * CINP + c4 * 4), src, ok ? 16 : 0);
        }
        asm volatile("cp.async.commit_group;");
    };

    ull acc[8];
    #pragma unroll
    for (int i = 0; i < 8; ++i) acc[i] = 0ull;

    issue(0, 0);
    for (int k = 0; k < K3; ++k) {
        if (k < K3 - 1) {
            issue(k + 1, (k + 1) & 1);
            asm volatile("cp.async.wait_group 1;");
        } else {
            asm volatile("cp.async.wait_group 0;");
        }
        __syncthreads();
        const float* cw = sW + (k & 1) * CIN * 64;
        const float* cx = sX + (k & 1) * 64 * CINP;
        #pragma unroll
        for (int c = 0; c < CIN; c += 4) {
            float4 xs0 = *(const float4*)(cx + (ty * 2 + 0) * CINP + c);
            float4 xs1 = *(const float4*)(cx + (ty * 2 + 1) * CINP + c);
            #pragma unroll
            for (int cc = 0; cc < 4; ++cc) {
                float4 wA = *(const float4*)(cw + (c + cc) * 64 + tx * 4);
                float4 wB = *(const float4*)(cw + (c + cc) * 64 + 32 + tx * 4);
                ull wa0 = pack2(wA.x, wA.y), wa1 = pack2(wA.z, wA.w);
                ull wb0 = pack2(wB.x, wB.y), wb1 = pack2(wB.z, wB.w);
                float x0 = ((const float*)&xs0)[cc];
                float x1 = ((const float*)&xs1)[cc];
                ull p0 = pack2(x0, x0), p1 = pack2(x1, x1);
                acc[0] = ffma2(p0, wa0, acc[0]);
                acc[1] = ffma2(p0, wa1, acc[1]);
                acc[2] = ffma2(p0, wb0, acc[2]);
                acc[3] = ffma2(p0, wb1, acc[3]);
                acc[4] = ffma2(p1, wa0, acc[4]);
                acc[5] = ffma2(p1, wa1, acc[5]);
                acc[6] = ffma2(p1, wb0, acc[6]);
                acc[7] = ffma2(p1, wb1, acc[7]);
            }
        }
        __syncthreads();
    }

    float4 bA = *(const float4*)(b + tx * 4);
    float4 bB = *(const float4*)(b + 32 + tx * 4);
    #pragma unroll
    for (int i = 0; i < 2; ++i) {
        int v = vb + ty * 2 + i;
        if (v < N_COARSE) {
            float2 rA0 = unpack2(acc[4 * i + 0]);
            float2 rA1 = unpack2(acc[4 * i + 1]);
            float2 rB0 = unpack2(acc[4 * i + 2]);
            float2 rB1 = unpack2(acc[4 * i + 3]);
            float4 oA = make_float4(fmaxf(rA0.x + bA.x, 0.f), fmaxf(rA0.y + bA.y, 0.f),
                                    fmaxf(rA1.x + bA.z, 0.f), fmaxf(rA1.y + bA.w, 0.f));
            float4 oB = make_float4(fmaxf(rB0.x + bB.x, 0.f), fmaxf(rB0.y + bB.y, 0.f),
                                    fmaxf(rB1.x + bB.z, 0.f), fmaxf(rB1.y + bB.w, 0.f));
            *(float4*)(out + v * 64 + tx * 4)      = oA;
            *(float4*)(out + v * 64 + 32 + tx * 4) = oB;
        }
    }
}

// ---------------- shared 64x64 GEMM + bias + relu on a 64-voxel tile (stride-68 smem) ----------------
__device__ __forceinline__ void gemm64x64_relu(const float* __restrict__ sx,
                                               const float* __restrict__ sw,
                                               const float* __restrict__ sb,
                                               float* __restrict__ so,
                                               int tx, int ty) {
    ull acc[8];
    #pragma unroll
    for (int i = 0; i < 8; ++i) acc[i] = 0ull;
    #pragma unroll
    for (int c = 0; c < 64; c += 4) {
        float4 xs[4];
        #pragma unroll
        for (int i = 0; i < 4; ++i)
            xs[i] = *(const float4*)(sx + (ty * 4 + i) * 68 + c);
        #pragma unroll
        for (int cc = 0; cc < 4; ++cc) {
            float4 w = *(const float4*)(sw + (c + cc) * 64 + tx * 4);
            ull w01 = pack2(w.x, w.y), w23 = pack2(w.z, w.w);
            #pragma unroll
            for (int i = 0; i < 4; ++i) {
                float xv = ((const float*)&xs[i])[cc];
                ull xx = pack2(xv, xv);
                acc[2 * i]     = ffma2(xx, w01, acc[2 * i]);
                acc[2 * i + 1] = ffma2(xx, w23, acc[2 * i + 1]);
            }
        }
    }
    float2 b01 = *(const float2*)(sb + tx * 4);
    float2 b23 = *(const float2*)(sb + tx * 4 + 2);
    #pragma unroll
    for (int i = 0; i < 4; ++i) {
        float2 r01 = unpack2(acc[2 * i]);
        float2 r23 = unpack2(acc[2 * i + 1]);
        float4 o = make_float4(fmaxf(r01.x + b01.x, 0.f), fmaxf(r01.y + b01.y, 0.f),
                               fmaxf(r23.x + b23.x, 0.f), fmaxf(r23.y + b23.y, 0.f));
        *(float4*)(so + (ty * 4 + i) * 68 + tx * 4) = o;
    }
}

// ---------------- fused t-conv + decoder: per-offset bucketed GEMM pipeline ----------------
// grid = (GX, 8). Block keeps W_t[off], W_d1, W_d2, biases in smem; tiles of 64 fine voxels.
__global__ void __launch_bounds__(256)
fused_kernel(const float* __restrict__ x3, const int* __restrict__ parent,
             const float* __restrict__ Wt, const float* __restrict__ bt,
             const float* __restrict__ Wd1, const float* __restrict__ bd1,
             const float* __restrict__ Wd2, const float* __restrict__ bd2,
             const float* __restrict__ xup, float* __restrict__ out) {
    extern __shared__ float dsm[];
    float* sWt = dsm;              // 4096
    float* sW1 = sWt + 4096;       // 4096
    float* sW2 = sW1 + 4096;       // 2048
    float* sg  = sW2 + 2048;       // 64*68
    float* st  = sg + 64 * 68;     // 64*68
    float* sbt = st + 64 * 68;     // 64
    float* sb1 = sbt + 64;         // 64
    float* sb2 = sb1 + 64;         // 32
    int*   smv = (int*)(sb2 + 32); // 64
    int*   spv = smv + 64;         // 64

    const int tid = threadIdx.x;
    const int off = blockIdx.y;
    const int cnt = g_cnt[off];
    const int* list = g_list + off * M_FINE;

    // one-time weight/bias loads
    {
        const float4* w = (const float4*)(Wt + off * 4096);
        #pragma unroll
        for (int r = 0; r < 4; ++r) ((float4*)sWt)[tid + 256 * r] = w[tid + 256 * r];
        const float4* w1 = (const float4*)Wd1;
        #pragma unroll
        for (int r = 0; r < 4; ++r) ((float4*)sW1)[tid + 256 * r] = w1[tid + 256 * r];
        const float4* w2 = (const float4*)Wd2;
        #pragma unroll
        for (int r = 0; r < 2; ++r) ((float4*)sW2)[tid + 256 * r] = w2[tid + 256 * r];
        if (tid < 64) { sbt[tid] = bt[tid]; sb1[tid] = bd1[tid]; }
        if (tid < 32) sb2[tid] = bd2[tid];
    }

    const int tx = tid & 15, ty = tid >> 4;     // stage1/2 tiling
    const int tx3 = tid & 31, ty3 = tid >> 5;   // stage3 tiling

    for (int tile = blockIdx.x; tile * 64 < cnt; tile += gridDim.x) {
        __syncthreads();
        if (tid < 64) {
            int j = tile * 64 + tid;
            int m = (j < cnt) ? list[j] : -1;
            smv[tid] = m;
            spv[tid] = (m >= 0) ? parent[m] : N_COARSE;
        }
        __syncthreads();
        // gather parent features (64 rows x 64 ch)
        #pragma unroll
        for (int r = 0; r < 4; ++r) {
            int i = tid + 256 * r;
            int v = i >> 4, c4 = i & 15;
            int p = spv[v];
            float4 val = make_float4(0.f, 0.f, 0.f, 0.f);
            if (p < N_COARSE) val = *(const float4*)(x3 + p * 64 + c4 * 4);
            *(float4*)(sg + v * 68 + c4 * 4) = val;
        }
        __syncthreads();
        gemm64x64_relu(sg, sWt, sbt, st, tx, ty);   // t = relu(g @ Wt[off] + bt)
        __syncthreads();
        gemm64x64_relu(st, sW1, sb1, sg, tx, ty);   // y = relu(t @ Wd1 + bd1)
        __syncthreads();
        // stage3: z = y @ Wd2 + bd2; out = z + xup (voxel-pair packed)
        ull a[4];
        #pragma unroll
        for (int q = 0; q < 4; ++q) a[q] = 0ull;
        #pragma unroll
        for (int c = 0; c < 64; c += 4) {
            float4 ys[8];
            #pragma unroll
            for (int j = 0; j < 8; ++j)
                ys[j] = *(const float4*)(sg + (ty3 * 8 + j) * 68 + c);
            #pragma unroll
            for (int cc = 0; cc < 4; ++cc) {
                float w = sW2[(c + cc) * 32 + tx3];
                ull ww = pack2(w, w);
                #pragma unroll
                for (int q = 0; q < 4; ++q) {
                    float y0 = ((const float*)&ys[2 * q])[cc];
                    float y1 = ((const float*)&ys[2 * q + 1])[cc];
                    a[q] = ffma2(pack2(y0, y1), ww, a[q]);
                }
            }
        }
        float b2 = sb2[tx3];
        #pragma unroll
        for (int q = 0; q < 4; ++q) {
            float2 z = unpack2(a[q]);
            int v0 = ty3 * 8 + 2 * q;
            int m0 = smv[v0], m1 = smv[v0 + 1];
            if (m0 >= 0) out[m0 * 32 + tx3] = z.x + b2 + xup[m0 * 32 + tx3];
            if (m1 >= 0) out[m1 * 32 + tx3] = z.y + b2 + xup[m1 * 32 + tx3];
        }
    }
}

// ---------------- launch ----------------
extern "C" void kernel_launch(void* const* d_in, const int* in_sizes, int n_in,
                              void* d_out, int out_size) {
    const float* feats  = (const float*)d_in[0];   // [N,32]
    const float* xup    = (const float*)d_in[1];   // [M,32]
    const int*   nbr    = (const int*)d_in[2];     // [N,27]
    const int*   parent = (const int*)d_in[3];     // [M]
    const int*   offs   = (const int*)d_in[4];     // [M]
    const float* We1 = (const float*)d_in[5];
    const float* be1 = (const float*)d_in[6];
    const float* We2 = (const float*)d_in[7];
    const float* be2 = (const float*)d_in[8];
    const float* We3 = (const float*)d_in[9];
    const float* be3 = (const float*)d_in[10];
    const float* Wt  = (const float*)d_in[11];
    const float* bt  = (const float*)d_in[12];
    const float* Wd1 = (const float*)d_in[13];
    const float* bd1 = (const float*)d_in[14];
    const float* Wd2 = (const float*)d_in[15];
    const float* bd2 = (const float*)d_in[16];
    float* out = (float*)d_out;

    float *pA, *pB;
    cudaGetSymbolAddress((void**)&pA, g_bufA);
    cudaGetSymbolAddress((void**)&pB, g_bufB);

    const int smem32 = (2 * 32 * 64 + 2 * 64 * 36) * 4 + 64 * K3 * 4;   // 41728
    const int smem64 = (2 * 64 * 64 + 2 * 64 * 68) * 4 + 64 * K3 * 4;   // 74496
    const int smemF  = (4096 + 4096 + 2048 + 2 * 64 * 68 + 160) * 4 + 128 * 4;

    cudaFuncSetAttribute(conv3_pipe<32>, cudaFuncAttributeMaxDynamicSharedMemorySize, smem32);
    cudaFuncSetAttribute(conv3_pipe<64>, cudaFuncAttributeMaxDynamicSharedMemorySize, smem64);
    cudaFuncSetAttribute(fused_kernel,   cudaFuncAttributeMaxDynamicSharedMemorySize, smemF);

    reset_kernel<<<1, 32>>>();
    bucket_kernel<<<(M_FINE + 255) / 256, 256>>>(offs);

    const int nblk = (N_COARSE + 63) / 64;  // 1563
    conv3_pipe<32><<<nblk, 256, smem32>>>(feats, nbr, We1, be1, pA);
    conv3_pipe<64><<<nblk, 256, smem64>>>(pA,    nbr, We2, be2, pB);
    conv3_pipe<64><<<nblk, 256, smem64>>>(pB,    nbr, We3, be3, pA);

    fused_kernel<<<dim3(128, 8), 256, smemF>>>(pA, parent, Wt, bt, Wd1, bd1,
                                               Wd2, bd2, xup, out);
}